// round 9
// baseline (speedup 1.0000x reference)
#include <cuda_runtime.h>
#include <cuda_bf16.h>
#include <cstdint>

#define E  8
#define DD 512
#define H1 512
#define H2 256
#define YD 256
#define BB 8192
#define TM 128
#define MAX_ROWS (BB + E * TM)        // 9216
#define MAX_TILES (MAX_ROWS / TM)     // 72

// ===================== helpers =====================
__device__ __forceinline__ uint32_t smem_u32(const void* p) {
    uint32_t a;
    asm("{ .reg .u64 t; cvta.to.shared.u64 t, %1; cvt.u32.u64 %0, t; }" : "=r"(a) : "l"(p));
    return a;
}
__device__ __forceinline__ void cp16(uint32_t dst, const void* src) {
    asm volatile("cp.async.cg.shared.global [%0], [%1], 16;" :: "r"(dst), "l"(src));
}
__device__ __forceinline__ void cp_commit() {
    asm volatile("cp.async.commit_group;" ::: "memory");
}
template <int N>
__device__ __forceinline__ void cp_wait() {
    asm volatile("cp.async.wait_group %0;" :: "n"(N) : "memory");
}
__device__ __forceinline__ void ldsm4(uint32_t* r, uint32_t addr) {
    asm volatile("ldmatrix.sync.aligned.m8n8.x4.shared.b16 {%0,%1,%2,%3}, [%4];"
        : "=r"(r[0]), "=r"(r[1]), "=r"(r[2]), "=r"(r[3]) : "r"(addr));
}
__device__ __forceinline__ void mma16816(float* c, const uint32_t* a, const uint32_t* b) {
    asm volatile("mma.sync.aligned.m16n8k16.row.col.f32.bf16.bf16.f32 "
        "{%0,%1,%2,%3}, {%4,%5,%6,%7}, {%8,%9}, {%0,%1,%2,%3};"
        : "+f"(c[0]), "+f"(c[1]), "+f"(c[2]), "+f"(c[3])
        : "r"(a[0]), "r"(a[1]), "r"(a[2]), "r"(a[3]), "r"(b[0]), "r"(b[1]));
}
__device__ __forceinline__ uint32_t pk2(__nv_bfloat16 a, __nv_bfloat16 b) {
    return (uint32_t)__bfloat16_as_ushort(a) | ((uint32_t)__bfloat16_as_ushort(b) << 16);
}

// ===================== scratch =====================
__device__ __nv_bfloat16 g_Ah[MAX_ROWS * DD],  g_Al[MAX_ROWS * DD];
__device__ __nv_bfloat16 g_a1h[MAX_ROWS * H1], g_a1l[MAX_ROWS * H1];
__device__ __nv_bfloat16 g_a2h[MAX_ROWS * H2], g_a2l[MAX_ROWS * H2];
__device__ __nv_bfloat16 g_W1h[E * H1 * DD],   g_W1l[E * H1 * DD];   // [e][n][k]
__device__ __nv_bfloat16 g_W2h[E * H2 * H1],   g_W2l[E * H2 * H1];
__device__ __nv_bfloat16 g_W3h[E * YD * H2],   g_W3l[E * YD * H2];
__device__ int g_perm[MAX_ROWS];
__device__ int g_padoff[E + 1];

// ===================== fused routing (one CTA) =====================
__global__ void __launch_bounds__(1024) route_all(const int* __restrict__ gate32) {
    __shared__ int s_cnt[E], s_off[E + 1], s_cur[E], s_nz;
    const int tid = threadIdx.x;
    if (tid == 0) s_nz = 0;
    if (tid < E) { s_cnt[tid] = 0; s_cur[tid] = 0; }
    __syncthreads();
    if (tid < 512 && gate32[2 * tid + 1] != 0) atomicOr(&s_nz, 1);
    __syncthreads();
    const int is64 = (s_nz == 0);

    auto gate = [&](int i) -> int {
        int e = is64 ? (int)((const long long*)gate32)[i] : gate32[i];
        return e < 0 ? 0 : (e > E - 1 ? E - 1 : e);
    };

    for (int i = tid; i < MAX_ROWS; i += 1024) g_perm[i] = -1;
    for (int i = tid; i < BB; i += 1024) atomicAdd(&s_cnt[gate(i)], 1);
    __syncthreads();

    if (tid == 0) {
        int off = 0;
        #pragma unroll
        for (int e = 0; e < E; e++) {
            s_off[e] = off; g_padoff[e] = off;
            off += ((s_cnt[e] + TM - 1) / TM) * TM;
        }
        s_off[E] = off; g_padoff[E] = off;
    }
    __syncthreads();

    for (int i = tid; i < BB; i += 1024) {
        int e = gate(i);
        g_perm[s_off[e] + atomicAdd(&s_cur[e], 1)] = i;
    }
}

// ===================== fused weight conversion =====================
__global__ void conv_w_all(const float* __restrict__ W1, const float* __restrict__ W2,
                           const float* __restrict__ W3) {
    __shared__ float s[32][33];
    const int b = blockIdx.x;
    const float* W; __nv_bfloat16 *Wh, *Wl;
    int K, N, e, kt, nt;
    if (b < 2048) {
        W = W1; Wh = g_W1h; Wl = g_W1l; K = DD; N = H1;
        e = b >> 8; kt = (b >> 4) & 15; nt = b & 15;
    } else if (b < 3072) {
        const int r = b - 2048;
        W = W2; Wh = g_W2h; Wl = g_W2l; K = H1; N = H2;
        e = r >> 7; kt = (r >> 3) & 15; nt = r & 7;
    } else {
        const int r = b - 3072;
        W = W3; Wh = g_W3h; Wl = g_W3l; K = H2; N = YD;
        e = r >> 6; kt = (r >> 3) & 7; nt = r & 7;
    }
    const float* Wp = W + (size_t)e * K * N;
    const int n0 = nt * 32, k0 = kt * 32;
    #pragma unroll
    for (int i = 0; i < 32; i += 8)
        s[threadIdx.y + i][threadIdx.x] = Wp[(size_t)(k0 + threadIdx.y + i) * N + n0 + threadIdx.x];
    __syncthreads();
    #pragma unroll
    for (int i = 0; i < 32; i += 8) {
        const int n = threadIdx.y + i, k = threadIdx.x;
        float v = s[k][n];
        __nv_bfloat16 h = __float2bfloat16(v);
        __nv_bfloat16 l = __float2bfloat16(v - __bfloat162float(h));
        size_t o = ((size_t)e * N + n0 + n) * (size_t)K + k0 + k;
        Wh[o] = h; Wl[o] = l;
    }
}

// layer-1 A: gather h rows via perm, split hi/lo
__global__ void conv_a(const float* __restrict__ h) {
    int idx = blockIdx.x * 256 + threadIdx.x;
    if (idx >= MAX_ROWS * (DD / 4)) return;
    int p = idx >> 7, kq = idx & 127;
    int orig = g_perm[p];
    float4 v = make_float4(0.f, 0.f, 0.f, 0.f);
    if (orig >= 0) v = *(const float4*)(h + (size_t)orig * DD + kq * 4);
    __nv_bfloat16 h0 = __float2bfloat16(v.x), h1 = __float2bfloat16(v.y);
    __nv_bfloat16 h2 = __float2bfloat16(v.z), h3 = __float2bfloat16(v.w);
    __nv_bfloat16 l0 = __float2bfloat16(v.x - __bfloat162float(h0));
    __nv_bfloat16 l1 = __float2bfloat16(v.y - __bfloat162float(h1));
    __nv_bfloat16 l2 = __float2bfloat16(v.z - __bfloat162float(h2));
    __nv_bfloat16 l3 = __float2bfloat16(v.w - __bfloat162float(h3));
    size_t o = (size_t)p * DD + kq * 4;
    *(uint2*)(g_Ah + o) = make_uint2(pk2(h0, h1), pk2(h2, h3));
    *(uint2*)(g_Al + o) = make_uint2(pk2(l0, l1), pk2(l2, l3));
}

// ===================== warp-MMA grouped GEMM =====================
// CTA 128x128, 8 warps (4 in M x 2 in N), warp tile 32x64.
// K chunks of 64 bf16 (SW128), cp.async double-buffered.
// Inner loop: ks-fragment double buffering (LDSM for ks+1 before MMAs of ks)
// + term-major MMA order (all h*h, then h*l, then l*h) for acc-RAW distance 16.

#define MAT 16384
#define BUF (4 * MAT)
#define GEMM_SMEM (2 * BUF)           // 131072

template <int K, int NT, int MODE>
__global__ void __launch_bounds__(256, 1) moe_gemm(
    const __nv_bfloat16* __restrict__ Ah, const __nv_bfloat16* __restrict__ Al,
    const __nv_bfloat16* __restrict__ Bh, const __nv_bfloat16* __restrict__ Bl,
    const float* __restrict__ bias,
    __nv_bfloat16* __restrict__ Oh, __nv_bfloat16* __restrict__ Ol,
    float* __restrict__ Of)
{
    const int row0 = blockIdx.y * TM;
    if (row0 >= g_padoff[E]) return;
    const int n0 = blockIdx.x * 128;

    int e = 0;
    #pragma unroll
    for (int j = 1; j < E; j++)
        if (row0 >= g_padoff[j]) e = j;

    extern __shared__ char smem[];
    const uint32_t sbase = smem_u32(smem);
    const int tid = threadIdx.x;
    const int wid = tid >> 5, lane = tid & 31;
    const int wm = wid & 3, wn = wid >> 2;    // 4 x 2 warp grid

    const __nv_bfloat16* Ahp = Ah + (size_t)row0 * K;
    const __nv_bfloat16* Alp = Al + (size_t)row0 * K;
    const __nv_bfloat16* Bhp = Bh + ((size_t)e * NT + n0) * (size_t)K;
    const __nv_bfloat16* Blp = Bl + ((size_t)e * NT + n0) * (size_t)K;

    constexpr int C = K / 64;

    const int lr[4] = { (tid + 0)   >> 3, (tid + 256) >> 3,
                        (tid + 512) >> 3, (tid + 768) >> 3 };
    const int lseg  = tid & 7;
    uint32_t lso[4];
    #pragma unroll
    for (int s = 0; s < 4; s++)
        lso[s] = (uint32_t)(lr[s] * 128 + ((lseg ^ (lr[s] & 7)) << 4));

    auto load_chunk = [&](int c, int buf) {
        const uint32_t sb = sbase + buf * BUF;
        #pragma unroll
        for (int s = 0; s < 4; s++) {
            const size_t go = (size_t)lr[s] * K + c * 64 + lseg * 8;
            cp16(sb + lso[s],           Ahp + go);
            cp16(sb + MAT + lso[s],     Alp + go);
            cp16(sb + 2 * MAT + lso[s], Bhp + go);
            cp16(sb + 3 * MAT + lso[s], Blp + go);
        }
        cp_commit();
    };

    const int arow_lo = wm * 32 + (lane & 15);
    const int akh = lane >> 4;
    const int nrow_lo = (lane & 7) + ((lane >> 4) << 3);
    const int bkh = (lane >> 3) & 1;

    float acc[2][8][4];
    #pragma unroll
    for (int mi = 0; mi < 2; mi++)
        #pragma unroll
        for (int ni = 0; ni < 8; ni++)
            #pragma unroll
            for (int q = 0; q < 4; q++) acc[mi][ni][q] = 0.f;

    // ks-double-buffered fragments
    uint32_t ah[2][2][4], al[2][2][4];     // [buf][mi][4]
    uint32_t bh[2][8][2], bl[2][8][2];     // [buf][ni][2]

    auto ldfrags = [&](int ks, int fb, uint32_t sb) {
        #pragma unroll
        for (int mi = 0; mi < 2; mi++) {
            const int r = arow_lo + mi * 16;
            const int seg = ks * 2 + akh;
            const uint32_t off = (uint32_t)(r * 128 + ((seg ^ (r & 7)) << 4));
            ldsm4(ah[fb][mi], sb + off);
            ldsm4(al[fb][mi], sb + MAT + off);
        }
        #pragma unroll
        for (int np = 0; np < 4; np++) {
            const int r = wn * 64 + np * 16 + nrow_lo;
            const int seg = ks * 2 + bkh;
            const uint32_t off = (uint32_t)(r * 128 + ((seg ^ (r & 7)) << 4));
            uint32_t t4[4];
            ldsm4(t4, sb + 2 * MAT + off);
            bh[fb][np * 2][0] = t4[0]; bh[fb][np * 2][1] = t4[1];
            bh[fb][np * 2 + 1][0] = t4[2]; bh[fb][np * 2 + 1][1] = t4[3];
            ldsm4(t4, sb + 3 * MAT + off);
            bl[fb][np * 2][0] = t4[0]; bl[fb][np * 2][1] = t4[1];
            bl[fb][np * 2 + 1][0] = t4[2]; bl[fb][np * 2 + 1][1] = t4[3];
        }
    };

    load_chunk(0, 0);

    for (int c = 0; c < C; c++) {
        if (c + 1 < C) { load_chunk(c + 1, (c + 1) & 1); cp_wait<1>(); }
        else cp_wait<0>();
        __syncthreads();

        const uint32_t sb = sbase + (c & 1) * BUF;
        ldfrags(0, 0, sb);
        #pragma unroll
        for (int ks = 0; ks < 4; ks++) {
            const int cur = ks & 1;
            if (ks < 3) ldfrags(ks + 1, cur ^ 1, sb);
            // term-major: max acc-reuse distance
            #pragma unroll
            for (int mi = 0; mi < 2; mi++)
                #pragma unroll
                for (int ni = 0; ni < 8; ni++)
                    mma16816(acc[mi][ni], ah[cur][mi], bh[cur][ni]);
            #pragma unroll
            for (int mi = 0; mi < 2; mi++)
                #pragma unroll
                for (int ni = 0; ni < 8; ni++)
                    mma16816(acc[mi][ni], ah[cur][mi], bl[cur][ni]);
            #pragma unroll
            for (int mi = 0; mi < 2; mi++)
                #pragma unroll
                for (int ni = 0; ni < 8; ni++)
                    mma16816(acc[mi][ni], al[cur][mi], bh[cur][ni]);
        }
        __syncthreads();
    }

    // ---- epilogue ----
    const float* bp = bias + (size_t)e * NT;
    const int qrow = lane >> 2;
    const int qcol = (lane & 3) * 2;

    #pragma unroll
    for (int mi = 0; mi < 2; mi++) {
        #pragma unroll
        for (int rh = 0; rh < 2; rh++) {
            const int rl = wm * 32 + mi * 16 + qrow + rh * 8;
            const int grow = row0 + rl;
            int orig = 0;
            if (MODE == 1) orig = g_perm[grow];
            #pragma unroll
            for (int ni = 0; ni < 8; ni++) {
                const int col = n0 + wn * 64 + ni * 8 + qcol;
                const float2 bb = *(const float2*)(bp + col);
                float v0 = acc[mi][ni][rh * 2 + 0] + bb.x;
                float v1 = acc[mi][ni][rh * 2 + 1] + bb.y;
                if (MODE == 0) {
                    v0 = v0 > 0.f ? v0 : 0.2f * v0;
                    v1 = v1 > 0.f ? v1 : 0.2f * v1;
                    __nv_bfloat16 h0 = __float2bfloat16(v0), h1 = __float2bfloat16(v1);
                    __nv_bfloat16 l0 = __float2bfloat16(v0 - __bfloat162float(h0));
                    __nv_bfloat16 l1 = __float2bfloat16(v1 - __bfloat162float(h1));
                    *(uint32_t*)(Oh + (size_t)grow * NT + col) = pk2(h0, h1);
                    *(uint32_t*)(Ol + (size_t)grow * NT + col) = pk2(l0, l1);
                } else {
                    if (orig >= 0)
                        *(float2*)(Of + (size_t)orig * NT + col) = make_float2(v0, v1);
                }
            }
        }
    }
}

// ===================== launch =====================
extern "C" void kernel_launch(void* const* d_in, const int* in_sizes, int n_in,
                              void* d_out, int out_size) {
    const float* h    = (const float*)d_in[0];
    const int*   gate = (const int*)  d_in[1];
    const float* W1   = (const float*)d_in[2];
    const float* b1   = (const float*)d_in[3];
    const float* W2   = (const float*)d_in[4];
    const float* b2   = (const float*)d_in[5];
    const float* W3   = (const float*)d_in[6];
    const float* b3   = (const float*)d_in[7];
    float* out = (float*)d_out;

    cudaFuncSetAttribute(moe_gemm<DD, H1, 0>, cudaFuncAttributeMaxDynamicSharedMemorySize, GEMM_SMEM);
    cudaFuncSetAttribute(moe_gemm<H1, H2, 0>, cudaFuncAttributeMaxDynamicSharedMemorySize, GEMM_SMEM);
    cudaFuncSetAttribute(moe_gemm<H2, YD, 1>, cudaFuncAttributeMaxDynamicSharedMemorySize, GEMM_SMEM);

    __nv_bfloat16 *ah, *al, *a1h, *a1l, *a2h, *a2l, *w1h, *w1l, *w2h, *w2l, *w3h, *w3l;
    cudaGetSymbolAddress((void**)&ah,  g_Ah);  cudaGetSymbolAddress((void**)&al,  g_Al);
    cudaGetSymbolAddress((void**)&a1h, g_a1h); cudaGetSymbolAddress((void**)&a1l, g_a1l);
    cudaGetSymbolAddress((void**)&a2h, g_a2h); cudaGetSymbolAddress((void**)&a2l, g_a2l);
    cudaGetSymbolAddress((void**)&w1h, g_W1h); cudaGetSymbolAddress((void**)&w1l, g_W1l);
    cudaGetSymbolAddress((void**)&w2h, g_W2h); cudaGetSymbolAddress((void**)&w2l, g_W2l);
    cudaGetSymbolAddress((void**)&w3h, g_W3h); cudaGetSymbolAddress((void**)&w3l, g_W3l);

    route_all<<<1, 1024>>>(gate);
    conv_w_all<<<3584, dim3(32, 8)>>>(W1, W2, W3);
    conv_a<<<(MAX_ROWS * (DD / 4) + 255) / 256, 256>>>(h);

    moe_gemm<DD, H1, 0><<<dim3(H1 / 128, MAX_TILES), 256, GEMM_SMEM>>>(
        ah, al, w1h, w1l, b1, a1h, a1l, nullptr);
    moe_gemm<H1, H2, 0><<<dim3(H2 / 128, MAX_TILES), 256, GEMM_SMEM>>>(
        a1h, a1l, w2h, w2l, b2, a2h, a2l, nullptr);
    moe_gemm<H2, YD, 1><<<dim3(YD / 128, MAX_TILES), 256, GEMM_SMEM>>>(
        a2h, a2l, w3h, w3l, b3, nullptr, nullptr, out);
}

// round 10
// speedup vs baseline: 2.4788x; 2.4788x over previous
#include <cuda_runtime.h>
#include <cuda_bf16.h>
#include <cuda_fp16.h>
#include <cstdint>

#define E  8
#define DD 512
#define H1 512
#define H2 256
#define YD 256
#define BB 8192
#define TM 128
#define MAX_ROWS (BB + E * TM)        // 9216
#define MAX_TILES (MAX_ROWS / TM)     // 72

// ===================== helpers =====================
__device__ __forceinline__ uint32_t smem_u32(const void* p) {
    uint32_t a;
    asm("{ .reg .u64 t; cvta.to.shared.u64 t, %1; cvt.u32.u64 %0, t; }" : "=r"(a) : "l"(p));
    return a;
}
__device__ __forceinline__ void cp16(uint32_t dst, const void* src) {
    asm volatile("cp.async.cg.shared.global [%0], [%1], 16;" :: "r"(dst), "l"(src));
}
__device__ __forceinline__ void cp_commit() {
    asm volatile("cp.async.commit_group;" ::: "memory");
}
template <int N>
__device__ __forceinline__ void cp_wait() {
    asm volatile("cp.async.wait_group %0;" :: "n"(N) : "memory");
}
__device__ __forceinline__ void ldsm4(uint32_t* r, uint32_t addr) {
    asm volatile("ldmatrix.sync.aligned.m8n8.x4.shared.b16 {%0,%1,%2,%3}, [%4];"
        : "=r"(r[0]), "=r"(r[1]), "=r"(r[2]), "=r"(r[3]) : "r"(addr));
}
__device__ __forceinline__ void mma_bf16(float* c, const uint32_t* a, const uint32_t* b) {
    asm volatile("mma.sync.aligned.m16n8k16.row.col.f32.bf16.bf16.f32 "
        "{%0,%1,%2,%3}, {%4,%5,%6,%7}, {%8,%9}, {%0,%1,%2,%3};"
        : "+f"(c[0]), "+f"(c[1]), "+f"(c[2]), "+f"(c[3])
        : "r"(a[0]), "r"(a[1]), "r"(a[2]), "r"(a[3]), "r"(b[0]), "r"(b[1]));
}
__device__ __forceinline__ void mma_f16(float* c, const uint32_t* a, const uint32_t* b) {
    asm volatile("mma.sync.aligned.m16n8k16.row.col.f32.f16.f16.f32 "
        "{%0,%1,%2,%3}, {%4,%5,%6,%7}, {%8,%9}, {%0,%1,%2,%3};"
        : "+f"(c[0]), "+f"(c[1]), "+f"(c[2]), "+f"(c[3])
        : "r"(a[0]), "r"(a[1]), "r"(a[2]), "r"(a[3]), "r"(b[0]), "r"(b[1]));
}
__device__ __forceinline__ uint32_t pk2(__nv_bfloat16 a, __nv_bfloat16 b) {
    return (uint32_t)__bfloat16_as_ushort(a) | ((uint32_t)__bfloat16_as_ushort(b) << 16);
}
__device__ __forceinline__ uint32_t pk2h(__half a, __half b) {
    return (uint32_t)__half_as_ushort(a) | ((uint32_t)__half_as_ushort(b) << 16);
}

// ===================== scratch =====================
__device__ __half        g_A16[MAX_ROWS * DD];        // gathered h, fp16
__device__ __half        g_a1[MAX_ROWS * H1];         // layer-1 out, fp16
__device__ __nv_bfloat16 g_a2h[MAX_ROWS * H2], g_a2l[MAX_ROWS * H2]; // layer-2 out split
__device__ __half        g_W1[E * H1 * DD];           // [e][n][k] fp16
__device__ __half        g_W2[E * H2 * H1];
__device__ __nv_bfloat16 g_W3h[E * YD * H2], g_W3l[E * YD * H2];     // split
__device__ int g_perm[MAX_ROWS];
__device__ int g_padoff[E + 1];

// ===================== fused routing (one CTA) =====================
__global__ void __launch_bounds__(1024) route_all(const int* __restrict__ gate32) {
    __shared__ int s_cnt[E], s_off[E + 1], s_cur[E], s_nz;
    const int tid = threadIdx.x;
    if (tid == 0) s_nz = 0;
    if (tid < E) { s_cnt[tid] = 0; s_cur[tid] = 0; }
    __syncthreads();
    if (tid < 512 && gate32[2 * tid + 1] != 0) atomicOr(&s_nz, 1);
    __syncthreads();
    const int is64 = (s_nz == 0);

    auto gate = [&](int i) -> int {
        int e = is64 ? (int)((const long long*)gate32)[i] : gate32[i];
        return e < 0 ? 0 : (e > E - 1 ? E - 1 : e);
    };

    for (int i = tid; i < MAX_ROWS; i += 1024) g_perm[i] = -1;
    for (int i = tid; i < BB; i += 1024) atomicAdd(&s_cnt[gate(i)], 1);
    __syncthreads();

    if (tid == 0) {
        int off = 0;
        #pragma unroll
        for (int e = 0; e < E; e++) {
            s_off[e] = off; g_padoff[e] = off;
            off += ((s_cnt[e] + TM - 1) / TM) * TM;
        }
        s_off[E] = off; g_padoff[E] = off;
    }
    __syncthreads();

    for (int i = tid; i < BB; i += 1024) {
        int e = gate(i);
        g_perm[s_off[e] + atomicAdd(&s_cur[e], 1)] = i;
    }
}

// ===================== fused conversion (weights + A gather) =====================
// blocks 0..2047: W1 -> fp16 [e][n][k]; 2048..3071: W2 -> fp16;
// 3072..3583: W3 -> bf16 hi/lo; 3584..8191: A gather -> fp16.
__global__ void __launch_bounds__(256) conv_all(
    const float* __restrict__ W1, const float* __restrict__ W2,
    const float* __restrict__ W3, const float* __restrict__ h)
{
    const int b = blockIdx.x;
    const int tid = threadIdx.x;

    if (b >= 3584) {  // ---- A gather + fp16 ----
        int idx = (b - 3584) * 256 + tid;       // one float4 per thread
        if (idx >= MAX_ROWS * (DD / 4)) return;
        int p = idx >> 7, kq = idx & 127;
        int orig = g_perm[p];
        float4 v = make_float4(0.f, 0.f, 0.f, 0.f);
        if (orig >= 0) v = *(const float4*)(h + (size_t)orig * DD + kq * 4);
        uint2 o;
        o.x = pk2h(__float2half_rn(v.x), __float2half_rn(v.y));
        o.y = pk2h(__float2half_rn(v.z), __float2half_rn(v.w));
        *(uint2*)(g_A16 + (size_t)p * DD + kq * 4) = o;
        return;
    }

    // ---- weight transpose [E][K][N] -> [e][n][k] ----
    __shared__ float s[32][33];
    const int tx = tid & 31, ty = tid >> 5;
    const float* W; int K, N, e, kt, nt, mode;   // mode 0 = fp16, 1 = bf16 split
    __half* W16 = nullptr; __nv_bfloat16 *Wh = nullptr, *Wl = nullptr;
    if (b < 2048) {
        W = W1; W16 = g_W1; K = DD; N = H1; mode = 0;
        e = b >> 8; kt = (b >> 4) & 15; nt = b & 15;
    } else if (b < 3072) {
        const int r = b - 2048;
        W = W2; W16 = g_W2; K = H1; N = H2; mode = 0;
        e = r >> 7; kt = (r >> 3) & 15; nt = r & 7;
    } else {
        const int r = b - 3072;
        W = W3; Wh = g_W3h; Wl = g_W3l; K = H2; N = YD; mode = 1;
        e = r >> 6; kt = (r >> 3) & 7; nt = r & 7;
    }
    const float* Wp = W + (size_t)e * K * N;
    const int n0 = nt * 32, k0 = kt * 32;
    #pragma unroll
    for (int i = 0; i < 32; i += 8)
        s[ty + i][tx] = Wp[(size_t)(k0 + ty + i) * N + n0 + tx];
    __syncthreads();
    #pragma unroll
    for (int i = 0; i < 32; i += 8) {
        const int n = ty + i, k = tx;
        float v = s[k][n];
        size_t o = ((size_t)e * N + n0 + n) * (size_t)K + k0 + k;
        if (mode == 0) {
            W16[o] = __float2half_rn(v);
        } else {
            __nv_bfloat16 hh = __float2bfloat16(v);
            Wh[o] = hh;
            Wl[o] = __float2bfloat16(v - __bfloat162float(hh));
        }
    }
}

// ===================== fp16 single-pass grouped GEMM (layers 1, 2) =====
// CTA 128x128, 8 warps (4M x 2N), warp tile 32x64. K chunks of 64 (SW128),
// cp.async double-buffered. OUT 0: bias+leaky -> fp16. OUT 1: bias+leaky -> bf16 hi/lo.

#define MAT 16384
#define BUF16 (2 * MAT)               // A, B
#define GEMM16_SMEM (2 * BUF16)       // 65536

template <int K, int NT, int OUT>
__global__ void __launch_bounds__(256, 2) gemm16(
    const __half* __restrict__ A, const __half* __restrict__ B,
    const float* __restrict__ bias,
    __half* __restrict__ O16,
    __nv_bfloat16* __restrict__ Obh, __nv_bfloat16* __restrict__ Obl)
{
    const int row0 = blockIdx.y * TM;
    if (row0 >= g_padoff[E]) return;
    const int n0 = blockIdx.x * 128;

    int e = 0;
    #pragma unroll
    for (int j = 1; j < E; j++)
        if (row0 >= g_padoff[j]) e = j;

    extern __shared__ char smem[];
    const uint32_t sbase = smem_u32(smem);
    const int tid = threadIdx.x;
    const int wid = tid >> 5, lane = tid & 31;
    const int wm = wid & 3, wn = wid >> 2;

    const __half* Ap = A + (size_t)row0 * K;
    const __half* Bp = B + ((size_t)e * NT + n0) * (size_t)K;

    constexpr int C = K / 64;

    const int lr[4] = { (tid + 0)   >> 3, (tid + 256) >> 3,
                        (tid + 512) >> 3, (tid + 768) >> 3 };
    const int lseg  = tid & 7;
    uint32_t lso[4];
    #pragma unroll
    for (int s = 0; s < 4; s++)
        lso[s] = (uint32_t)(lr[s] * 128 + ((lseg ^ (lr[s] & 7)) << 4));

    auto load_chunk = [&](int c, int buf) {
        const uint32_t sb = sbase + buf * BUF16;
        #pragma unroll
        for (int s = 0; s < 4; s++) {
            const size_t go = (size_t)lr[s] * K + c * 64 + lseg * 8;
            cp16(sb + lso[s],       Ap + go);
            cp16(sb + MAT + lso[s], Bp + go);
        }
        cp_commit();
    };

    const int arow_lo = wm * 32 + (lane & 15);
    const int akh = lane >> 4;
    const int nrow_lo = (lane & 7) + ((lane >> 4) << 3);
    const int bkh = (lane >> 3) & 1;

    float acc[2][8][4];
    #pragma unroll
    for (int mi = 0; mi < 2; mi++)
        #pragma unroll
        for (int ni = 0; ni < 8; ni++)
            #pragma unroll
            for (int q = 0; q < 4; q++) acc[mi][ni][q] = 0.f;

    load_chunk(0, 0);

    for (int c = 0; c < C; c++) {
        if (c + 1 < C) { load_chunk(c + 1, (c + 1) & 1); cp_wait<1>(); }
        else cp_wait<0>();
        __syncthreads();

        const uint32_t sb = sbase + (c & 1) * BUF16;
        #pragma unroll
        for (int ks = 0; ks < 4; ks++) {
            uint32_t af[2][4];
            #pragma unroll
            for (int mi = 0; mi < 2; mi++) {
                const int r = arow_lo + mi * 16;
                const int seg = ks * 2 + akh;
                const uint32_t off = (uint32_t)(r * 128 + ((seg ^ (r & 7)) << 4));
                ldsm4(af[mi], sb + off);
            }
            uint32_t bf[8][2];
            #pragma unroll
            for (int np = 0; np < 4; np++) {
                const int r = wn * 64 + np * 16 + nrow_lo;
                const int seg = ks * 2 + bkh;
                const uint32_t off = (uint32_t)(r * 128 + ((seg ^ (r & 7)) << 4));
                uint32_t t4[4];
                ldsm4(t4, sb + MAT + off);
                bf[np * 2][0] = t4[0]; bf[np * 2][1] = t4[1];
                bf[np * 2 + 1][0] = t4[2]; bf[np * 2 + 1][1] = t4[3];
            }
            #pragma unroll
            for (int mi = 0; mi < 2; mi++)
                #pragma unroll
                for (int ni = 0; ni < 8; ni++)
                    mma_f16(acc[mi][ni], af[mi], bf[ni]);
        }
        __syncthreads();
    }

    // ---- epilogue: bias + leaky ----
    const float* bp = bias + (size_t)e * NT;
    const int qrow = lane >> 2;
    const int qcol = (lane & 3) * 2;

    #pragma unroll
    for (int mi = 0; mi < 2; mi++) {
        #pragma unroll
        for (int rh = 0; rh < 2; rh++) {
            const int rl = wm * 32 + mi * 16 + qrow + rh * 8;
            const int grow = row0 + rl;
            #pragma unroll
            for (int ni = 0; ni < 8; ni++) {
                const int col = n0 + wn * 64 + ni * 8 + qcol;
                const float2 bb = *(const float2*)(bp + col);
                float v0 = acc[mi][ni][rh * 2 + 0] + bb.x;
                float v1 = acc[mi][ni][rh * 2 + 1] + bb.y;
                v0 = v0 > 0.f ? v0 : 0.2f * v0;
                v1 = v1 > 0.f ? v1 : 0.2f * v1;
                if (OUT == 0) {
                    *(uint32_t*)(O16 + (size_t)grow * NT + col) =
                        pk2h(__float2half_rn(v0), __float2half_rn(v1));
                } else {
                    __nv_bfloat16 h0 = __float2bfloat16(v0), h1 = __float2bfloat16(v1);
                    __nv_bfloat16 l0 = __float2bfloat16(v0 - __bfloat162float(h0));
                    __nv_bfloat16 l1 = __float2bfloat16(v1 - __bfloat162float(h1));
                    *(uint32_t*)(Obh + (size_t)grow * NT + col) = pk2(h0, h1);
                    *(uint32_t*)(Obl + (size_t)grow * NT + col) = pk2(l0, l1);
                }
            }
        }
    }
}

// ===================== layer-3: bf16 split-3 GEMM, fp32 scatter ==========
#define BUF3 (4 * MAT)
#define GEMM3_SMEM (2 * BUF3)         // 131072

__global__ void __launch_bounds__(256, 1) gemm3(
    const __nv_bfloat16* __restrict__ Ah, const __nv_bfloat16* __restrict__ Al,
    const __nv_bfloat16* __restrict__ Bh, const __nv_bfloat16* __restrict__ Bl,
    const float* __restrict__ bias, float* __restrict__ Of)
{
    constexpr int K = H2, NT = YD;
    const int row0 = blockIdx.y * TM;
    if (row0 >= g_padoff[E]) return;
    const int n0 = blockIdx.x * 128;

    int e = 0;
    #pragma unroll
    for (int j = 1; j < E; j++)
        if (row0 >= g_padoff[j]) e = j;

    extern __shared__ char smem[];
    const uint32_t sbase = smem_u32(smem);
    const int tid = threadIdx.x;
    const int wid = tid >> 5, lane = tid & 31;
    const int wm = wid & 3, wn = wid >> 2;

    const __nv_bfloat16* Ahp = Ah + (size_t)row0 * K;
    const __nv_bfloat16* Alp = Al + (size_t)row0 * K;
    const __nv_bfloat16* Bhp = Bh + ((size_t)e * NT + n0) * (size_t)K;
    const __nv_bfloat16* Blp = Bl + ((size_t)e * NT + n0) * (size_t)K;

    constexpr int C = K / 64;

    const int lr[4] = { (tid + 0)   >> 3, (tid + 256) >> 3,
                        (tid + 512) >> 3, (tid + 768) >> 3 };
    const int lseg  = tid & 7;
    uint32_t lso[4];
    #pragma unroll
    for (int s = 0; s < 4; s++)
        lso[s] = (uint32_t)(lr[s] * 128 + ((lseg ^ (lr[s] & 7)) << 4));

    auto load_chunk = [&](int c, int buf) {
        const uint32_t sb = sbase + buf * BUF3;
        #pragma unroll
        for (int s = 0; s < 4; s++) {
            const size_t go = (size_t)lr[s] * K + c * 64 + lseg * 8;
            cp16(sb + lso[s],           Ahp + go);
            cp16(sb + MAT + lso[s],     Alp + go);
            cp16(sb + 2 * MAT + lso[s], Bhp + go);
            cp16(sb + 3 * MAT + lso[s], Blp + go);
        }
        cp_commit();
    };

    const int arow_lo = wm * 32 + (lane & 15);
    const int akh = lane >> 4;
    const int nrow_lo = (lane & 7) + ((lane >> 4) << 3);
    const int bkh = (lane >> 3) & 1;

    float acc[2][8][4];
    #pragma unroll
    for (int mi = 0; mi < 2; mi++)
        #pragma unroll
        for (int ni = 0; ni < 8; ni++)
            #pragma unroll
            for (int q = 0; q < 4; q++) acc[mi][ni][q] = 0.f;

    load_chunk(0, 0);

    for (int c = 0; c < C; c++) {
        if (c + 1 < C) { load_chunk(c + 1, (c + 1) & 1); cp_wait<1>(); }
        else cp_wait<0>();
        __syncthreads();

        const uint32_t sb = sbase + (c & 1) * BUF3;
        #pragma unroll
        for (int ks = 0; ks < 4; ks++) {
            uint32_t ah[2][4], al[2][4];
            #pragma unroll
            for (int mi = 0; mi < 2; mi++) {
                const int r = arow_lo + mi * 16;
                const int seg = ks * 2 + akh;
                const uint32_t off = (uint32_t)(r * 128 + ((seg ^ (r & 7)) << 4));
                ldsm4(ah[mi], sb + off);
                ldsm4(al[mi], sb + MAT + off);
            }
            uint32_t bh[8][2], bl[8][2];
            #pragma unroll
            for (int np = 0; np < 4; np++) {
                const int r = wn * 64 + np * 16 + nrow_lo;
                const int seg = ks * 2 + bkh;
                const uint32_t off = (uint32_t)(r * 128 + ((seg ^ (r & 7)) << 4));
                uint32_t t4[4];
                ldsm4(t4, sb + 2 * MAT + off);
                bh[np * 2][0] = t4[0]; bh[np * 2][1] = t4[1];
                bh[np * 2 + 1][0] = t4[2]; bh[np * 2 + 1][1] = t4[3];
                ldsm4(t4, sb + 3 * MAT + off);
                bl[np * 2][0] = t4[0]; bl[np * 2][1] = t4[1];
                bl[np * 2 + 1][0] = t4[2]; bl[np * 2 + 1][1] = t4[3];
            }
            #pragma unroll
            for (int mi = 0; mi < 2; mi++)
                #pragma unroll
                for (int ni = 0; ni < 8; ni++) {
                    mma_bf16(acc[mi][ni], ah[mi], bh[ni]);
                    mma_bf16(acc[mi][ni], ah[mi], bl[ni]);
                    mma_bf16(acc[mi][ni], al[mi], bh[ni]);
                }
        }
        __syncthreads();
    }

    const float* bp = bias + (size_t)e * NT;
    const int qrow = lane >> 2;
    const int qcol = (lane & 3) * 2;

    #pragma unroll
    for (int mi = 0; mi < 2; mi++) {
        #pragma unroll
        for (int rh = 0; rh < 2; rh++) {
            const int rl = wm * 32 + mi * 16 + qrow + rh * 8;
            const int orig = g_perm[row0 + rl];
            if (orig < 0) continue;
            #pragma unroll
            for (int ni = 0; ni < 8; ni++) {
                const int col = n0 + wn * 64 + ni * 8 + qcol;
                const float2 bb = *(const float2*)(bp + col);
                *(float2*)(Of + (size_t)orig * NT + col) =
                    make_float2(acc[mi][ni][rh * 2 + 0] + bb.x,
                                acc[mi][ni][rh * 2 + 1] + bb.y);
            }
        }
    }
}

// ===================== launch =====================
extern "C" void kernel_launch(void* const* d_in, const int* in_sizes, int n_in,
                              void* d_out, int out_size) {
    const float* h    = (const float*)d_in[0];
    const int*   gate = (const int*)  d_in[1];
    const float* W1   = (const float*)d_in[2];
    const float* b1   = (const float*)d_in[3];
    const float* W2   = (const float*)d_in[4];
    const float* b2   = (const float*)d_in[5];
    const float* W3   = (const float*)d_in[6];
    const float* b3   = (const float*)d_in[7];
    float* out = (float*)d_out;

    cudaFuncSetAttribute(gemm16<DD, H1, 0>, cudaFuncAttributeMaxDynamicSharedMemorySize, GEMM16_SMEM);
    cudaFuncSetAttribute(gemm16<H1, H2, 1>, cudaFuncAttributeMaxDynamicSharedMemorySize, GEMM16_SMEM);
    cudaFuncSetAttribute(gemm3, cudaFuncAttributeMaxDynamicSharedMemorySize, GEMM3_SMEM);

    __half *a16, *a1, *w1, *w2;
    __nv_bfloat16 *a2h, *a2l, *w3h, *w3l;
    cudaGetSymbolAddress((void**)&a16, g_A16);
    cudaGetSymbolAddress((void**)&a1,  g_a1);
    cudaGetSymbolAddress((void**)&w1,  g_W1);
    cudaGetSymbolAddress((void**)&w2,  g_W2);
    cudaGetSymbolAddress((void**)&a2h, g_a2h); cudaGetSymbolAddress((void**)&a2l, g_a2l);
    cudaGetSymbolAddress((void**)&w3h, g_W3h); cudaGetSymbolAddress((void**)&w3l, g_W3l);

    route_all<<<1, 1024>>>(gate);
    conv_all<<<3584 + (MAX_ROWS * (DD / 4) + 255) / 256, 256>>>(W1, W2, W3, h);

    gemm16<DD, H1, 0><<<dim3(H1 / 128, MAX_TILES), 256, GEMM16_SMEM>>>(
        a16, w1, b1, a1, nullptr, nullptr);
    gemm16<H1, H2, 1><<<dim3(H2 / 128, MAX_TILES), 256, GEMM16_SMEM>>>(
        a1, w2, b2, nullptr, a2h, a2l);
    gemm3<<<dim3(YD / 128, MAX_TILES), 256, GEMM3_SMEM>>>(
        a2h, a2l, w3h, w3l, b3, out);
}

// round 11
// speedup vs baseline: 2.8608x; 1.1541x over previous
#include <cuda_runtime.h>
#include <cuda_bf16.h>
#include <cuda_fp16.h>
#include <cstdint>

#define E  8
#define DD 512
#define H1 512
#define H2 256
#define YD 256
#define BB 8192
#define TM 128
#define MAX_ROWS (BB + E * TM)        // 9216
#define MAX_TILES (MAX_ROWS / TM)     // 72

// ===================== helpers =====================
__device__ __forceinline__ uint32_t smem_u32(const void* p) {
    uint32_t a;
    asm("{ .reg .u64 t; cvta.to.shared.u64 t, %1; cvt.u32.u64 %0, t; }" : "=r"(a) : "l"(p));
    return a;
}
__device__ __forceinline__ void cp16(uint32_t dst, const void* src) {
    asm volatile("cp.async.cg.shared.global [%0], [%1], 16;" :: "r"(dst), "l"(src));
}
__device__ __forceinline__ void cp_commit() {
    asm volatile("cp.async.commit_group;" ::: "memory");
}
template <int N>
__device__ __forceinline__ void cp_wait() {
    asm volatile("cp.async.wait_group %0;" :: "n"(N) : "memory");
}
__device__ __forceinline__ void ldsm4(uint32_t* r, uint32_t addr) {
    asm volatile("ldmatrix.sync.aligned.m8n8.x4.shared.b16 {%0,%1,%2,%3}, [%4];"
        : "=r"(r[0]), "=r"(r[1]), "=r"(r[2]), "=r"(r[3]) : "r"(addr));
}
__device__ __forceinline__ void mma_f16(float* c, const uint32_t* a, const uint32_t* b) {
    asm volatile("mma.sync.aligned.m16n8k16.row.col.f32.f16.f16.f32 "
        "{%0,%1,%2,%3}, {%4,%5,%6,%7}, {%8,%9}, {%0,%1,%2,%3};"
        : "+f"(c[0]), "+f"(c[1]), "+f"(c[2]), "+f"(c[3])
        : "r"(a[0]), "r"(a[1]), "r"(a[2]), "r"(a[3]), "r"(b[0]), "r"(b[1]));
}
__device__ __forceinline__ uint32_t pk2h(__half a, __half b) {
    return (uint32_t)__half_as_ushort(a) | ((uint32_t)__half_as_ushort(b) << 16);
}

// ===================== scratch =====================
__device__ __half g_A16[MAX_ROWS * DD];     // gathered h, fp16
__device__ __half g_a1[MAX_ROWS * H1];      // layer-1 out, fp16
__device__ __half g_a2[MAX_ROWS * H2];      // layer-2 out, fp16
__device__ __half g_W1[E * H1 * DD];        // [e][n][k] fp16
__device__ __half g_W2[E * H2 * H1];
__device__ __half g_W3[E * YD * H2];
__device__ int g_perm[MAX_ROWS];
__device__ int g_padoff[E + 1];

// ===================== fused routing (one CTA) =====================
__global__ void __launch_bounds__(1024) route_all(const int* __restrict__ gate32) {
    __shared__ int s_cnt[E], s_off[E + 1], s_cur[E], s_nz;
    const int tid = threadIdx.x;
    if (tid == 0) s_nz = 0;
    if (tid < E) { s_cnt[tid] = 0; s_cur[tid] = 0; }
    __syncthreads();
    if (tid < 512 && gate32[2 * tid + 1] != 0) atomicOr(&s_nz, 1);
    __syncthreads();
    const int is64 = (s_nz == 0);

    auto gate = [&](int i) -> int {
        int e = is64 ? (int)((const long long*)gate32)[i] : gate32[i];
        return e < 0 ? 0 : (e > E - 1 ? E - 1 : e);
    };

    for (int i = tid; i < MAX_ROWS; i += 1024) g_perm[i] = -1;
    for (int i = tid; i < BB; i += 1024) atomicAdd(&s_cnt[gate(i)], 1);
    __syncthreads();

    if (tid == 0) {
        int off = 0;
        #pragma unroll
        for (int e = 0; e < E; e++) {
            s_off[e] = off; g_padoff[e] = off;
            off += ((s_cnt[e] + TM - 1) / TM) * TM;
        }
        s_off[E] = off; g_padoff[E] = off;
    }
    __syncthreads();

    for (int i = tid; i < BB; i += 1024) {
        int e = gate(i);
        g_perm[s_off[e] + atomicAdd(&s_cur[e], 1)] = i;
    }
}

// ===================== fused conversion (weights + A gather), all fp16 ====
// blocks 0..2047: W1; 2048..3071: W2; 3072..3583: W3; 3584+: A gather.
__global__ void __launch_bounds__(256) conv_all(
    const float* __restrict__ W1, const float* __restrict__ W2,
    const float* __restrict__ W3, const float* __restrict__ h)
{
    const int b = blockIdx.x;
    const int tid = threadIdx.x;

    if (b >= 3584) {  // ---- A gather + fp16 ----
        int idx = (b - 3584) * 256 + tid;
        if (idx >= MAX_ROWS * (DD / 4)) return;
        int p = idx >> 7, kq = idx & 127;
        int orig = g_perm[p];
        float4 v = make_float4(0.f, 0.f, 0.f, 0.f);
        if (orig >= 0) v = *(const float4*)(h + (size_t)orig * DD + kq * 4);
        uint2 o;
        o.x = pk2h(__float2half_rn(v.x), __float2half_rn(v.y));
        o.y = pk2h(__float2half_rn(v.z), __float2half_rn(v.w));
        *(uint2*)(g_A16 + (size_t)p * DD + kq * 4) = o;
        return;
    }

    // ---- weight transpose [E][K][N] -> [e][n][k], fp16 ----
    __shared__ float s[32][33];
    const int tx = tid & 31, ty = tid >> 5;
    const float* W; __half* W16; int K, N, e, kt, nt;
    if (b < 2048) {
        W = W1; W16 = g_W1; K = DD; N = H1;
        e = b >> 8; kt = (b >> 4) & 15; nt = b & 15;
    } else if (b < 3072) {
        const int r = b - 2048;
        W = W2; W16 = g_W2; K = H1; N = H2;
        e = r >> 7; kt = (r >> 3) & 15; nt = r & 7;
    } else {
        const int r = b - 3072;
        W = W3; W16 = g_W3; K = H2; N = YD;
        e = r >> 6; kt = (r >> 3) & 7; nt = r & 7;
    }
    const float* Wp = W + (size_t)e * K * N;
    const int n0 = nt * 32, k0 = kt * 32;
    #pragma unroll
    for (int i = 0; i < 32; i += 8)
        s[ty + i][tx] = Wp[(size_t)(k0 + ty + i) * N + n0 + tx];
    __syncthreads();
    #pragma unroll
    for (int i = 0; i < 32; i += 8) {
        const int n = ty + i, k = tx;
        W16[((size_t)e * N + n0 + n) * (size_t)K + k0 + k] = __float2half_rn(s[k][n]);
    }
}

// ===================== fp16 grouped GEMM =====================
// CTA TM x TNT (TNT = 128 or 64), 8 warps (4M x 2N), warp tile 32 x TNT/2.
// K chunks of 64 fp16 (SW128), cp.async double-buffered.
// MODE 0: bias + leaky -> fp16.  MODE 1: bias -> fp32 scatter via perm.

#define AMAT 16384

template <int K, int NT, int TNT, int MODE>
__global__ void __launch_bounds__(256, 2) gemm16u(
    const __half* __restrict__ A, const __half* __restrict__ B,
    const float* __restrict__ bias,
    __half* __restrict__ O16, float* __restrict__ Of)
{
    constexpr int BMAT = TNT * 128;          // B tile bytes
    constexpr int BUFB = AMAT + BMAT;
    constexpr int NI = TNT / 16;             // B frags per warp (8 or 4)
    constexpr int BNS = TNT / 32;            // B loader slots per thread

    const int row0 = blockIdx.y * TM;
    if (row0 >= g_padoff[E]) return;
    const int n0 = blockIdx.x * TNT;

    int e = 0;
    #pragma unroll
    for (int j = 1; j < E; j++)
        if (row0 >= g_padoff[j]) e = j;

    extern __shared__ char smem[];
    const uint32_t sbase = smem_u32(smem);
    const int tid = threadIdx.x;
    const int wid = tid >> 5, lane = tid & 31;
    const int wm = wid & 3, wn = wid >> 2;

    const __half* Ap = A + (size_t)row0 * K;
    const __half* Bp = B + ((size_t)e * NT + n0) * (size_t)K;

    constexpr int C = K / 64;

    const int lr[4] = { (tid + 0)   >> 3, (tid + 256) >> 3,
                        (tid + 512) >> 3, (tid + 768) >> 3 };
    const int lseg  = tid & 7;
    uint32_t lso[4];
    #pragma unroll
    for (int s = 0; s < 4; s++)
        lso[s] = (uint32_t)(lr[s] * 128 + ((lseg ^ (lr[s] & 7)) << 4));

    auto load_chunk = [&](int c, int buf) {
        const uint32_t sb = sbase + buf * BUFB;
        #pragma unroll
        for (int s = 0; s < 4; s++)
            cp16(sb + lso[s], Ap + (size_t)lr[s] * K + c * 64 + lseg * 8);
        #pragma unroll
        for (int s = 0; s < BNS; s++)
            cp16(sb + AMAT + lso[s], Bp + (size_t)lr[s] * K + c * 64 + lseg * 8);
        cp_commit();
    };

    const int arow_lo = wm * 32 + (lane & 15);
    const int akh = lane >> 4;
    const int nrow_lo = (lane & 7) + ((lane >> 4) << 3);
    const int bkh = (lane >> 3) & 1;

    float acc[2][NI][4];
    #pragma unroll
    for (int mi = 0; mi < 2; mi++)
        #pragma unroll
        for (int ni = 0; ni < NI; ni++)
            #pragma unroll
            for (int q = 0; q < 4; q++) acc[mi][ni][q] = 0.f;

    load_chunk(0, 0);

    for (int c = 0; c < C; c++) {
        if (c + 1 < C) { load_chunk(c + 1, (c + 1) & 1); cp_wait<1>(); }
        else cp_wait<0>();
        __syncthreads();

        const uint32_t sb = sbase + (c & 1) * BUFB;
        #pragma unroll
        for (int ks = 0; ks < 4; ks++) {
            uint32_t af[2][4];
            #pragma unroll
            for (int mi = 0; mi < 2; mi++) {
                const int r = arow_lo + mi * 16;
                const int seg = ks * 2 + akh;
                const uint32_t off = (uint32_t)(r * 128 + ((seg ^ (r & 7)) << 4));
                ldsm4(af[mi], sb + off);
            }
            uint32_t bf[NI][2];
            #pragma unroll
            for (int np = 0; np < NI / 2; np++) {
                const int r = wn * (TNT / 2) + np * 16 + nrow_lo;
                const int seg = ks * 2 + bkh;
                const uint32_t off = (uint32_t)(r * 128 + ((seg ^ (r & 7)) << 4));
                uint32_t t4[4];
                ldsm4(t4, sb + AMAT + off);
                bf[np * 2][0] = t4[0]; bf[np * 2][1] = t4[1];
                bf[np * 2 + 1][0] = t4[2]; bf[np * 2 + 1][1] = t4[3];
            }
            #pragma unroll
            for (int mi = 0; mi < 2; mi++)
                #pragma unroll
                for (int ni = 0; ni < NI; ni++)
                    mma_f16(acc[mi][ni], af[mi], bf[ni]);
        }
        __syncthreads();
    }

    // ---- epilogue ----
    const float* bp = bias + (size_t)e * NT;
    const int qrow = lane >> 2;
    const int qcol = (lane & 3) * 2;

    #pragma unroll
    for (int mi = 0; mi < 2; mi++) {
        #pragma unroll
        for (int rh = 0; rh < 2; rh++) {
            const int rl = wm * 32 + mi * 16 + qrow + rh * 8;
            const int grow = row0 + rl;
            int orig = 0;
            if (MODE == 1) { orig = g_perm[grow]; if (orig < 0) continue; }
            #pragma unroll
            for (int ni = 0; ni < NI; ni++) {
                const int col = n0 + wn * (TNT / 2) + ni * 8 + qcol;
                const float2 bb = *(const float2*)(bp + col);
                float v0 = acc[mi][ni][rh * 2 + 0] + bb.x;
                float v1 = acc[mi][ni][rh * 2 + 1] + bb.y;
                if (MODE == 0) {
                    v0 = v0 > 0.f ? v0 : 0.2f * v0;
                    v1 = v1 > 0.f ? v1 : 0.2f * v1;
                    *(uint32_t*)(O16 + (size_t)grow * NT + col) =
                        pk2h(__float2half_rn(v0), __float2half_rn(v1));
                } else {
                    *(float2*)(Of + (size_t)orig * NT + col) = make_float2(v0, v1);
                }
            }
        }
    }
}

// ===================== launch =====================
extern "C" void kernel_launch(void* const* d_in, const int* in_sizes, int n_in,
                              void* d_out, int out_size) {
    const float* h    = (const float*)d_in[0];
    const int*   gate = (const int*)  d_in[1];
    const float* W1   = (const float*)d_in[2];
    const float* b1   = (const float*)d_in[3];
    const float* W2   = (const float*)d_in[4];
    const float* b2   = (const float*)d_in[5];
    const float* W3   = (const float*)d_in[6];
    const float* b3   = (const float*)d_in[7];
    float* out = (float*)d_out;

    constexpr int SM128 = 2 * (AMAT + 128 * 128);   // 65536
    constexpr int SM64  = 2 * (AMAT + 64 * 128);    // 49152
    cudaFuncSetAttribute(gemm16u<DD, H1, 128, 0>, cudaFuncAttributeMaxDynamicSharedMemorySize, SM128);
    cudaFuncSetAttribute(gemm16u<H1, H2, 64, 0>,  cudaFuncAttributeMaxDynamicSharedMemorySize, SM64);
    cudaFuncSetAttribute(gemm16u<H2, YD, 64, 1>,  cudaFuncAttributeMaxDynamicSharedMemorySize, SM64);

    __half *a16, *a1, *a2, *w1, *w2, *w3;
    cudaGetSymbolAddress((void**)&a16, g_A16);
    cudaGetSymbolAddress((void**)&a1,  g_a1);
    cudaGetSymbolAddress((void**)&a2,  g_a2);
    cudaGetSymbolAddress((void**)&w1,  g_W1);
    cudaGetSymbolAddress((void**)&w2,  g_W2);
    cudaGetSymbolAddress((void**)&w3,  g_W3);

    route_all<<<1, 1024>>>(gate);
    conv_all<<<3584 + (MAX_ROWS * (DD / 4) + 255) / 256, 256>>>(W1, W2, W3, h);

    gemm16u<DD, H1, 128, 0><<<dim3(H1 / 128, MAX_TILES), 256, SM128>>>(
        a16, w1, b1, a1, nullptr);
    gemm16u<H1, H2, 64, 0><<<dim3(H2 / 64, MAX_TILES), 256, SM64>>>(
        a1, w2, b2, a2, nullptr);
    gemm16u<H2, YD, 64, 1><<<dim3(YD / 64, MAX_TILES), 256, SM64>>>(
        a2, w3, b3, nullptr, out);
}

// round 12
// speedup vs baseline: 2.9826x; 1.0426x over previous
#include <cuda_runtime.h>
#include <cuda_bf16.h>
#include <cuda_fp16.h>
#include <cstdint>

#define E  8
#define DD 512
#define H1 512
#define H2 256
#define YD 256
#define BB 8192
#define TM 128
#define MAX_ROWS (BB + E * TM)        // 9216
#define MAX_TILES (MAX_ROWS / TM)     // 72

// ===================== helpers =====================
__device__ __forceinline__ uint32_t smem_u32(const void* p) {
    uint32_t a;
    asm("{ .reg .u64 t; cvta.to.shared.u64 t, %1; cvt.u32.u64 %0, t; }" : "=r"(a) : "l"(p));
    return a;
}
__device__ __forceinline__ void cp16(uint32_t dst, const void* src) {
    asm volatile("cp.async.cg.shared.global [%0], [%1], 16;" :: "r"(dst), "l"(src));
}
__device__ __forceinline__ void cp_commit() {
    asm volatile("cp.async.commit_group;" ::: "memory");
}
template <int N>
__device__ __forceinline__ void cp_wait() {
    asm volatile("cp.async.wait_group %0;" :: "n"(N) : "memory");
}
__device__ __forceinline__ void ldsm4(uint32_t* r, uint32_t addr) {
    asm volatile("ldmatrix.sync.aligned.m8n8.x4.shared.b16 {%0,%1,%2,%3}, [%4];"
        : "=r"(r[0]), "=r"(r[1]), "=r"(r[2]), "=r"(r[3]) : "r"(addr));
}
__device__ __forceinline__ void mma_f16(float* c, const uint32_t* a, const uint32_t* b) {
    asm volatile("mma.sync.aligned.m16n8k16.row.col.f32.f16.f16.f32 "
        "{%0,%1,%2,%3}, {%4,%5,%6,%7}, {%8,%9}, {%0,%1,%2,%3};"
        : "+f"(c[0]), "+f"(c[1]), "+f"(c[2]), "+f"(c[3])
        : "r"(a[0]), "r"(a[1]), "r"(a[2]), "r"(a[3]), "r"(b[0]), "r"(b[1]));
}
__device__ __forceinline__ uint32_t pk2h(__half a, __half b) {
    return (uint32_t)__half_as_ushort(a) | ((uint32_t)__half_as_ushort(b) << 16);
}
#define SWZ(o) ((o) ^ (((o) >> 3) & 0x70))

// ===================== scratch =====================
__device__ __half g_A16[MAX_ROWS * DD];     // gathered h, fp16
__device__ __half g_a1[MAX_ROWS * H1];      // layer-1 out, fp16
__device__ __half g_W1[E * H1 * DD];        // [e][n][k] fp16
__device__ __half g_W2[E * H2 * H1];
__device__ __half g_W3[E * YD * H2];
__device__ int g_perm[MAX_ROWS];
__device__ int g_padoff[E + 1];

// ===================== fused routing (one CTA) =====================
__global__ void __launch_bounds__(1024) route_all(const int* __restrict__ gate32) {
    __shared__ int s_cnt[E], s_off[E + 1], s_cur[E], s_nz;
    const int tid = threadIdx.x;
    if (tid == 0) s_nz = 0;
    if (tid < E) { s_cnt[tid] = 0; s_cur[tid] = 0; }
    __syncthreads();
    if (tid < 512 && gate32[2 * tid + 1] != 0) atomicOr(&s_nz, 1);
    __syncthreads();
    const int is64 = (s_nz == 0);

    auto gate = [&](int i) -> int {
        int e = is64 ? (int)((const long long*)gate32)[i] : gate32[i];
        return e < 0 ? 0 : (e > E - 1 ? E - 1 : e);
    };

    for (int i = tid; i < MAX_ROWS; i += 1024) g_perm[i] = -1;
    for (int i = tid; i < BB; i += 1024) atomicAdd(&s_cnt[gate(i)], 1);
    __syncthreads();

    if (tid == 0) {
        int off = 0;
        #pragma unroll
        for (int e = 0; e < E; e++) {
            s_off[e] = off; g_padoff[e] = off;
            off += ((s_cnt[e] + TM - 1) / TM) * TM;
        }
        s_off[E] = off; g_padoff[E] = off;
    }
    __syncthreads();

    for (int i = tid; i < BB; i += 1024) {
        int e = gate(i);
        g_perm[s_off[e] + atomicAdd(&s_cur[e], 1)] = i;
    }
}

// ===================== fused conversion (weights + A gather), all fp16 ====
__global__ void __launch_bounds__(256) conv_all(
    const float* __restrict__ W1, const float* __restrict__ W2,
    const float* __restrict__ W3, const float* __restrict__ h)
{
    const int b = blockIdx.x;
    const int tid = threadIdx.x;

    if (b >= 3584) {  // ---- A gather + fp16 ----
        int idx = (b - 3584) * 256 + tid;
        if (idx >= MAX_ROWS * (DD / 4)) return;
        int p = idx >> 7, kq = idx & 127;
        int orig = g_perm[p];
        float4 v = make_float4(0.f, 0.f, 0.f, 0.f);
        if (orig >= 0) v = *(const float4*)(h + (size_t)orig * DD + kq * 4);
        uint2 o;
        o.x = pk2h(__float2half_rn(v.x), __float2half_rn(v.y));
        o.y = pk2h(__float2half_rn(v.z), __float2half_rn(v.w));
        *(uint2*)(g_A16 + (size_t)p * DD + kq * 4) = o;
        return;
    }

    __shared__ float s[32][33];
    const int tx = tid & 31, ty = tid >> 5;
    const float* W; __half* W16; int K, N, e, kt, nt;
    if (b < 2048) {
        W = W1; W16 = g_W1; K = DD; N = H1;
        e = b >> 8; kt = (b >> 4) & 15; nt = b & 15;
    } else if (b < 3072) {
        const int r = b - 2048;
        W = W2; W16 = g_W2; K = H1; N = H2;
        e = r >> 7; kt = (r >> 3) & 15; nt = r & 7;
    } else {
        const int r = b - 3072;
        W = W3; W16 = g_W3; K = H2; N = YD;
        e = r >> 6; kt = (r >> 3) & 7; nt = r & 7;
    }
    const float* Wp = W + (size_t)e * K * N;
    const int n0 = nt * 32, k0 = kt * 32;
    #pragma unroll
    for (int i = 0; i < 32; i += 8)
        s[ty + i][tx] = Wp[(size_t)(k0 + ty + i) * N + n0 + tx];
    __syncthreads();
    #pragma unroll
    for (int i = 0; i < 32; i += 8) {
        const int n = ty + i, k = tx;
        W16[((size_t)e * N + n0 + n) * (size_t)K + k0 + k] = __float2half_rn(s[k][n]);
    }
}

// ===================== layer-1 GEMM (128x128, fp16 single-pass) ==========
#define AMAT 16384
#define SM1 (2 * (AMAT + 128 * 128))   // 65536

__global__ void __launch_bounds__(256, 2) gemm1(
    const __half* __restrict__ A, const __half* __restrict__ B,
    const float* __restrict__ bias, __half* __restrict__ O16)
{
    constexpr int K = DD, NT = H1;
    const int row0 = blockIdx.y * TM;
    if (row0 >= g_padoff[E]) return;
    const int n0 = blockIdx.x * 128;

    int e = 0;
    #pragma unroll
    for (int j = 1; j < E; j++)
        if (row0 >= g_padoff[j]) e = j;

    extern __shared__ char smem[];
    const uint32_t sbase = smem_u32(smem);
    const int tid = threadIdx.x;
    const int wid = tid >> 5, lane = tid & 31;
    const int wm = wid & 3, wn = wid >> 2;

    const __half* Ap = A + (size_t)row0 * K;
    const __half* Bp = B + ((size_t)e * NT + n0) * (size_t)K;

    constexpr int C = K / 64;
    constexpr int BUFB = AMAT + 128 * 128;

    const int lr[4] = { (tid + 0)   >> 3, (tid + 256) >> 3,
                        (tid + 512) >> 3, (tid + 768) >> 3 };
    const int lseg  = tid & 7;
    uint32_t lso[4];
    #pragma unroll
    for (int s = 0; s < 4; s++)
        lso[s] = (uint32_t)(lr[s] * 128 + ((lseg ^ (lr[s] & 7)) << 4));

    auto load_chunk = [&](int c, int buf) {
        const uint32_t sb = sbase + buf * BUFB;
        #pragma unroll
        for (int s = 0; s < 4; s++) {
            const size_t go = (size_t)lr[s] * K + c * 64 + lseg * 8;
            cp16(sb + lso[s],        Ap + go);
            cp16(sb + AMAT + lso[s], Bp + go);
        }
        cp_commit();
    };

    const int arow_lo = wm * 32 + (lane & 15);
    const int akh = lane >> 4;
    const int nrow_lo = (lane & 7) + ((lane >> 4) << 3);
    const int bkh = (lane >> 3) & 1;

    float acc[2][8][4];
    #pragma unroll
    for (int mi = 0; mi < 2; mi++)
        #pragma unroll
        for (int ni = 0; ni < 8; ni++)
            #pragma unroll
            for (int q = 0; q < 4; q++) acc[mi][ni][q] = 0.f;

    load_chunk(0, 0);

    for (int c = 0; c < C; c++) {
        if (c + 1 < C) { load_chunk(c + 1, (c + 1) & 1); cp_wait<1>(); }
        else cp_wait<0>();
        __syncthreads();

        const uint32_t sb = sbase + (c & 1) * BUFB;
        #pragma unroll
        for (int ks = 0; ks < 4; ks++) {
            uint32_t af[2][4];
            #pragma unroll
            for (int mi = 0; mi < 2; mi++) {
                const int r = arow_lo + mi * 16;
                const int seg = ks * 2 + akh;
                const uint32_t off = (uint32_t)(r * 128 + ((seg ^ (r & 7)) << 4));
                ldsm4(af[mi], sb + off);
            }
            uint32_t bf[8][2];
            #pragma unroll
            for (int np = 0; np < 4; np++) {
                const int r = wn * 64 + np * 16 + nrow_lo;
                const int seg = ks * 2 + bkh;
                const uint32_t off = (uint32_t)(r * 128 + ((seg ^ (r & 7)) << 4));
                uint32_t t4[4];
                ldsm4(t4, sb + AMAT + off);
                bf[np * 2][0] = t4[0]; bf[np * 2][1] = t4[1];
                bf[np * 2 + 1][0] = t4[2]; bf[np * 2 + 1][1] = t4[3];
            }
            #pragma unroll
            for (int mi = 0; mi < 2; mi++)
                #pragma unroll
                for (int ni = 0; ni < 8; ni++)
                    mma_f16(acc[mi][ni], af[mi], bf[ni]);
        }
        __syncthreads();
    }

    const float* bp = bias + (size_t)e * NT;
    const int qrow = lane >> 2;
    const int qcol = (lane & 3) * 2;

    #pragma unroll
    for (int mi = 0; mi < 2; mi++) {
        #pragma unroll
        for (int rh = 0; rh < 2; rh++) {
            const int rl = wm * 32 + mi * 16 + qrow + rh * 8;
            const int grow = row0 + rl;
            #pragma unroll
            for (int ni = 0; ni < 8; ni++) {
                const int col = n0 + wn * 64 + ni * 8 + qcol;
                const float2 bb = *(const float2*)(bp + col);
                float v0 = acc[mi][ni][rh * 2 + 0] + bb.x;
                float v1 = acc[mi][ni][rh * 2 + 1] + bb.y;
                v0 = v0 > 0.f ? v0 : 0.2f * v0;
                v1 = v1 > 0.f ? v1 : 0.2f * v1;
                *(uint32_t*)(O16 + (size_t)grow * NT + col) =
                    pk2h(__float2half_rn(v0), __float2half_rn(v1));
            }
        }
    }
}

// ===================== fused layers 2+3 (64-row CTAs) ==========
// Stage 1: a2 = leaky(a1[64x512] @ W2^T + b2) -> SMEM fp16, SW128 chunks.
// Stage 2: out = a2 @ W3^T + b3 -> fp32 scatter via perm.
// SMEM: [0, 81920): stage-1 dbuf (A1 8KB + W2 32KB) x2 / stage-2 W3 dbuf 32KB x2
//       [81920, 114688): a2 tile (4 chunks x 8KB)
#define SM23 114688

__global__ void __launch_bounds__(256, 1) gemm23(
    const __half* __restrict__ A1, const __half* __restrict__ W2,
    const float* __restrict__ b2,  const __half* __restrict__ W3,
    const float* __restrict__ b3,  float* __restrict__ Of)
{
    const int row0 = blockIdx.x * 64;
    if (row0 >= g_padoff[E]) return;

    int e = 0;
    #pragma unroll
    for (int j = 1; j < E; j++)
        if (row0 >= g_padoff[j]) e = j;

    extern __shared__ char smem[];
    const uint32_t sbase = smem_u32(smem);
    const int tid = threadIdx.x;
    const int wid = tid >> 5, lane = tid & 31;
    const int wm = wid & 1, wn = wid >> 1;     // 2M x 4N warp grid

    const __half* Ap  = A1 + (size_t)row0 * H1;
    const __half* B2p = W2 + (size_t)e * H2 * H1;
    const __half* B3p = W3 + (size_t)e * YD * H2;

    const int lseg = tid & 7;
    int rA[2]; uint32_t loA[2];
    #pragma unroll
    for (int s = 0; s < 2; s++) {
        rA[s] = (tid + s * 256) >> 3;
        loA[s] = (uint32_t)(rA[s] * 128 + ((lseg ^ (rA[s] & 7)) << 4));
    }
    int rB[8]; uint32_t loB[8];
    #pragma unroll
    for (int s = 0; s < 8; s++) {
        rB[s] = (tid + s * 256) >> 3;
        loB[s] = (uint32_t)(rB[s] * 128 + ((lseg ^ (rB[s] & 7)) << 4));
    }

    auto load1 = [&](int c, int buf) {
        const uint32_t sb = sbase + buf * 40960;
        #pragma unroll
        for (int s = 0; s < 2; s++)
            cp16(sb + loA[s], Ap + (size_t)rA[s] * H1 + c * 64 + lseg * 8);
        #pragma unroll
        for (int s = 0; s < 8; s++)
            cp16(sb + 8192 + loB[s], B2p + (size_t)rB[s] * H1 + c * 64 + lseg * 8);
        cp_commit();
    };

    const int arow_lo = wm * 32 + (lane & 15);
    const int akh = lane >> 4;
    const int nrow_lo = (lane & 7) + ((lane >> 4) << 3);
    const int bkh = (lane >> 3) & 1;
    const int qrow = lane >> 2;
    const int qcol = (lane & 3) * 2;

    // ---------- stage 1 ----------
    float acc[2][8][4];
    #pragma unroll
    for (int mi = 0; mi < 2; mi++)
        #pragma unroll
        for (int ni = 0; ni < 8; ni++)
            #pragma unroll
            for (int q = 0; q < 4; q++) acc[mi][ni][q] = 0.f;

    load1(0, 0);
    for (int c = 0; c < 8; c++) {
        if (c + 1 < 8) { load1(c + 1, (c + 1) & 1); cp_wait<1>(); }
        else cp_wait<0>();
        __syncthreads();

        const uint32_t sb = sbase + (c & 1) * 40960;
        #pragma unroll
        for (int ks = 0; ks < 4; ks++) {
            uint32_t af[2][4];
            #pragma unroll
            for (int mi = 0; mi < 2; mi++) {
                const int r = arow_lo + mi * 16;
                const int seg = ks * 2 + akh;
                const uint32_t off = (uint32_t)(r * 128 + ((seg ^ (r & 7)) << 4));
                ldsm4(af[mi], sb + off);
            }
            uint32_t bf[8][2];
            #pragma unroll
            for (int np = 0; np < 4; np++) {
                const int r = wn * 64 + np * 16 + nrow_lo;
                const int seg = ks * 2 + bkh;
                const uint32_t off = (uint32_t)(r * 128 + ((seg ^ (r & 7)) << 4));
                uint32_t t4[4];
                ldsm4(t4, sb + 8192 + off);
                bf[np * 2][0] = t4[0]; bf[np * 2][1] = t4[1];
                bf[np * 2 + 1][0] = t4[2]; bf[np * 2 + 1][1] = t4[3];
            }
            #pragma unroll
            for (int mi = 0; mi < 2; mi++)
                #pragma unroll
                for (int ni = 0; ni < 8; ni++)
                    mma_f16(acc[mi][ni], af[mi], bf[ni]);
        }
        __syncthreads();
    }

    // stage-1 epilogue: leaky(acc + b2) -> a2 smem (fp16, SW128 chunks of 64 k-cols)
    {
        const float* bp = b2 + (size_t)e * H2;
        #pragma unroll
        for (int mi = 0; mi < 2; mi++) {
            #pragma unroll
            for (int rh = 0; rh < 2; rh++) {
                const int rl = wm * 32 + mi * 16 + qrow + rh * 8;
                #pragma unroll
                for (int ni = 0; ni < 8; ni++) {
                    const int col = wn * 64 + ni * 8 + qcol;
                    const float2 bb = *(const float2*)(bp + col);
                    float v0 = acc[mi][ni][rh * 2 + 0] + bb.x;
                    float v1 = acc[mi][ni][rh * 2 + 1] + bb.y;
                    v0 = v0 > 0.f ? v0 : 0.2f * v0;
                    v1 = v1 > 0.f ? v1 : 0.2f * v1;
                    const uint32_t off = (uint32_t)(rl * 128 + (col & 63) * 2);
                    *(uint32_t*)(smem + 81920 + (col >> 6) * 8192 + SWZ(off)) =
                        pk2h(__float2half_rn(v0), __float2half_rn(v1));
                }
            }
        }
    }
    __syncthreads();

    // ---------- stage 2 ----------
    auto load3 = [&](int c, int buf) {
        const uint32_t sb = sbase + buf * 32768;
        #pragma unroll
        for (int s = 0; s < 8; s++)
            cp16(sb + loB[s], B3p + (size_t)rB[s] * H2 + c * 64 + lseg * 8);
        cp_commit();
    };

    float acc3[2][8][4];
    #pragma unroll
    for (int mi = 0; mi < 2; mi++)
        #pragma unroll
        for (int ni = 0; ni < 8; ni++)
            #pragma unroll
            for (int q = 0; q < 4; q++) acc3[mi][ni][q] = 0.f;

    load3(0, 0);
    for (int c = 0; c < 4; c++) {
        if (c + 1 < 4) { load3(c + 1, (c + 1) & 1); cp_wait<1>(); }
        else cp_wait<0>();
        __syncthreads();

        const uint32_t sb  = sbase + (c & 1) * 32768;
        const uint32_t a2b = sbase + 81920 + c * 8192;
        #pragma unroll
        for (int ks = 0; ks < 4; ks++) {
            uint32_t af[2][4];
            #pragma unroll
            for (int mi = 0; mi < 2; mi++) {
                const int r = arow_lo + mi * 16;
                const int seg = ks * 2 + akh;
                const uint32_t off = (uint32_t)(r * 128 + ((seg ^ (r & 7)) << 4));
                ldsm4(af[mi], a2b + off);
            }
            uint32_t bf[8][2];
            #pragma unroll
            for (int np = 0; np < 4; np++) {
                const int r = wn * 64 + np * 16 + nrow_lo;
                const int seg = ks * 2 + bkh;
                const uint32_t off = (uint32_t)(r * 128 + ((seg ^ (r & 7)) << 4));
                uint32_t t4[4];
                ldsm4(t4, sb + off);
                bf[np * 2][0] = t4[0]; bf[np * 2][1] = t4[1];
                bf[np * 2 + 1][0] = t4[2]; bf[np * 2 + 1][1] = t4[3];
            }
            #pragma unroll
            for (int mi = 0; mi < 2; mi++)
                #pragma unroll
                for (int ni = 0; ni < 8; ni++)
                    mma_f16(acc3[mi][ni], af[mi], bf[ni]);
        }
        __syncthreads();
    }

    // stage-2 epilogue: bias + scatter fp32
    {
        const float* bp = b3 + (size_t)e * YD;
        #pragma unroll
        for (int mi = 0; mi < 2; mi++) {
            #pragma unroll
            for (int rh = 0; rh < 2; rh++) {
                const int rl = wm * 32 + mi * 16 + qrow + rh * 8;
                const int orig = g_perm[row0 + rl];
                if (orig < 0) continue;
                #pragma unroll
                for (int ni = 0; ni < 8; ni++) {
                    const int col = wn * 64 + ni * 8 + qcol;
                    const float2 bb = *(const float2*)(bp + col);
                    *(float2*)(Of + (size_t)orig * YD + col) =
                        make_float2(acc3[mi][ni][rh * 2 + 0] + bb.x,
                                    acc3[mi][ni][rh * 2 + 1] + bb.y);
                }
            }
        }
    }
}

// ===================== launch =====================
extern "C" void kernel_launch(void* const* d_in, const int* in_sizes, int n_in,
                              void* d_out, int out_size) {
    const float* h    = (const float*)d_in[0];
    const int*   gate = (const int*)  d_in[1];
    const float* W1   = (const float*)d_in[2];
    const float* b1   = (const float*)d_in[3];
    const float* W2   = (const float*)d_in[4];
    const float* b2   = (const float*)d_in[5];
    const float* W3   = (const float*)d_in[6];
    const float* b3   = (const float*)d_in[7];
    float* out = (float*)d_out;

    cudaFuncSetAttribute(gemm1,  cudaFuncAttributeMaxDynamicSharedMemorySize, SM1);
    cudaFuncSetAttribute(gemm23, cudaFuncAttributeMaxDynamicSharedMemorySize, SM23);

    __half *a16, *a1, *w1, *w2, *w3;
    cudaGetSymbolAddress((void**)&a16, g_A16);
    cudaGetSymbolAddress((void**)&a1,  g_a1);
    cudaGetSymbolAddress((void**)&w1,  g_W1);
    cudaGetSymbolAddress((void**)&w2,  g_W2);
    cudaGetSymbolAddress((void**)&w3,  g_W3);

    route_all<<<1, 1024>>>(gate);
    conv_all<<<3584 + (MAX_ROWS * (DD / 4) + 255) / 256, 256>>>(W1, W2, W3, h);

    gemm1<<<dim3(H1 / 128, MAX_TILES), 256, SM1>>>(a16, w1, b1, a1);
    gemm23<<<MAX_TILES * 2, 256, SM23>>>(a1, w2, b2, w3, b3, out);
}

// round 13
// speedup vs baseline: 3.0157x; 1.0111x over previous
#include <cuda_runtime.h>
#include <cuda_bf16.h>
#include <cuda_fp16.h>
#include <cstdint>

#define E  8
#define DD 512
#define H1 512
#define H2 256
#define YD 256
#define BB 8192
#define TM 128
#define MAX_ROWS (BB + E * TM)        // 9216
#define MAX_TILES (MAX_ROWS / TM)     // 72

// ===================== helpers =====================
__device__ __forceinline__ uint32_t smem_u32(const void* p) {
    uint32_t a;
    asm("{ .reg .u64 t; cvta.to.shared.u64 t, %1; cvt.u32.u64 %0, t; }" : "=r"(a) : "l"(p));
    return a;
}
__device__ __forceinline__ void cp16(uint32_t dst, const void* src) {
    asm volatile("cp.async.cg.shared.global [%0], [%1], 16;" :: "r"(dst), "l"(src));
}
__device__ __forceinline__ void cp_commit() {
    asm volatile("cp.async.commit_group;" ::: "memory");
}
template <int N>
__device__ __forceinline__ void cp_wait() {
    asm volatile("cp.async.wait_group %0;" :: "n"(N) : "memory");
}
__device__ __forceinline__ void ldsm4(uint32_t* r, uint32_t addr) {
    asm volatile("ldmatrix.sync.aligned.m8n8.x4.shared.b16 {%0,%1,%2,%3}, [%4];"
        : "=r"(r[0]), "=r"(r[1]), "=r"(r[2]), "=r"(r[3]) : "r"(addr));
}
__device__ __forceinline__ void mma_f16(float* c, const uint32_t* a, const uint32_t* b) {
    asm volatile("mma.sync.aligned.m16n8k16.row.col.f32.f16.f16.f32 "
        "{%0,%1,%2,%3}, {%4,%5,%6,%7}, {%8,%9}, {%0,%1,%2,%3};"
        : "+f"(c[0]), "+f"(c[1]), "+f"(c[2]), "+f"(c[3])
        : "r"(a[0]), "r"(a[1]), "r"(a[2]), "r"(a[3]), "r"(b[0]), "r"(b[1]));
}
__device__ __forceinline__ uint32_t pk2h(__half a, __half b) {
    return (uint32_t)__half_as_ushort(a) | ((uint32_t)__half_as_ushort(b) << 16);
}
#define SWZ(o) ((o) ^ (((o) >> 3) & 0x70))

// ===================== scratch =====================
__device__ __half g_A16[MAX_ROWS * DD];     // gathered h, fp16
__device__ __half g_a1[MAX_ROWS * H1];      // layer-1 out, fp16
__device__ __half g_W1[E * H1 * DD];        // [e][n][k] fp16
__device__ __half g_W2[E * H2 * H1];
__device__ __half g_W3[E * YD * H2];
__device__ int g_perm[MAX_ROWS];
__device__ int g_padoff[E + 1];

// ===================== fused routing (one CTA) =====================
__global__ void __launch_bounds__(1024) route_all(const int* __restrict__ gate32) {
    __shared__ int s_cnt[E], s_off[E + 1], s_cur[E], s_nz;
    const int tid = threadIdx.x;
    if (tid == 0) s_nz = 0;
    if (tid < E) { s_cnt[tid] = 0; s_cur[tid] = 0; }
    __syncthreads();
    if (tid < 512 && gate32[2 * tid + 1] != 0) atomicOr(&s_nz, 1);
    __syncthreads();
    const int is64 = (s_nz == 0);

    auto gate = [&](int i) -> int {
        int e = is64 ? (int)((const long long*)gate32)[i] : gate32[i];
        return e < 0 ? 0 : (e > E - 1 ? E - 1 : e);
    };

    for (int i = tid; i < MAX_ROWS; i += 1024) g_perm[i] = -1;
    for (int i = tid; i < BB; i += 1024) atomicAdd(&s_cnt[gate(i)], 1);
    __syncthreads();

    if (tid == 0) {
        int off = 0;
        #pragma unroll
        for (int e = 0; e < E; e++) {
            s_off[e] = off; g_padoff[e] = off;
            off += ((s_cnt[e] + TM - 1) / TM) * TM;
        }
        s_off[E] = off; g_padoff[E] = off;
    }
    __syncthreads();

    for (int i = tid; i < BB; i += 1024) {
        int e = gate(i);
        g_perm[s_off[e] + atomicAdd(&s_cur[e], 1)] = i;
    }
}

// ===================== fused conversion (weights + A gather), all fp16 ====
__global__ void __launch_bounds__(256) conv_all(
    const float* __restrict__ W1, const float* __restrict__ W2,
    const float* __restrict__ W3, const float* __restrict__ h)
{
    const int b = blockIdx.x;
    const int tid = threadIdx.x;

    if (b >= 3584) {  // ---- A gather + fp16 ----
        int idx = (b - 3584) * 256 + tid;
        if (idx >= MAX_ROWS * (DD / 4)) return;
        int p = idx >> 7, kq = idx & 127;
        int orig = g_perm[p];
        float4 v = make_float4(0.f, 0.f, 0.f, 0.f);
        if (orig >= 0) v = *(const float4*)(h + (size_t)orig * DD + kq * 4);
        uint2 o;
        o.x = pk2h(__float2half_rn(v.x), __float2half_rn(v.y));
        o.y = pk2h(__float2half_rn(v.z), __float2half_rn(v.w));
        *(uint2*)(g_A16 + (size_t)p * DD + kq * 4) = o;
        return;
    }

    __shared__ float s[32][33];
    const int tx = tid & 31, ty = tid >> 5;
    const float* W; __half* W16; int K, N, e, kt, nt;
    if (b < 2048) {
        W = W1; W16 = g_W1; K = DD; N = H1;
        e = b >> 8; kt = (b >> 4) & 15; nt = b & 15;
    } else if (b < 3072) {
        const int r = b - 2048;
        W = W2; W16 = g_W2; K = H1; N = H2;
        e = r >> 7; kt = (r >> 3) & 15; nt = r & 7;
    } else {
        const int r = b - 3072;
        W = W3; W16 = g_W3; K = H2; N = YD;
        e = r >> 6; kt = (r >> 3) & 7; nt = r & 7;
    }
    const float* Wp = W + (size_t)e * K * N;
    const int n0 = nt * 32, k0 = kt * 32;
    #pragma unroll
    for (int i = 0; i < 32; i += 8)
        s[ty + i][tx] = Wp[(size_t)(k0 + ty + i) * N + n0 + tx];
    __syncthreads();
    #pragma unroll
    for (int i = 0; i < 32; i += 8) {
        const int n = ty + i, k = tx;
        W16[((size_t)e * N + n0 + n) * (size_t)K + k0 + k] = __float2half_rn(s[k][n]);
    }
}

// ===================== layer-1 GEMM (128x128, fp16 single-pass) ==========
#define AMAT 16384
#define SM1 (2 * (AMAT + 128 * 128))   // 65536

__global__ void __launch_bounds__(256, 2) gemm1(
    const __half* __restrict__ A, const __half* __restrict__ B,
    const float* __restrict__ bias, __half* __restrict__ O16)
{
    constexpr int K = DD, NT = H1;
    const int row0 = blockIdx.y * TM;
    if (row0 >= g_padoff[E]) return;
    const int n0 = blockIdx.x * 128;

    int e = 0;
    #pragma unroll
    for (int j = 1; j < E; j++)
        if (row0 >= g_padoff[j]) e = j;

    extern __shared__ char smem[];
    const uint32_t sbase = smem_u32(smem);
    const int tid = threadIdx.x;
    const int wid = tid >> 5, lane = tid & 31;
    const int wm = wid & 3, wn = wid >> 2;

    const __half* Ap = A + (size_t)row0 * K;
    const __half* Bp = B + ((size_t)e * NT + n0) * (size_t)K;

    constexpr int C = K / 64;
    constexpr int BUFB = AMAT + 128 * 128;

    const int lr[4] = { (tid + 0)   >> 3, (tid + 256) >> 3,
                        (tid + 512) >> 3, (tid + 768) >> 3 };
    const int lseg  = tid & 7;
    uint32_t lso[4];
    #pragma unroll
    for (int s = 0; s < 4; s++)
        lso[s] = (uint32_t)(lr[s] * 128 + ((lseg ^ (lr[s] & 7)) << 4));

    auto load_chunk = [&](int c, int buf) {
        const uint32_t sb = sbase + buf * BUFB;
        #pragma unroll
        for (int s = 0; s < 4; s++) {
            const size_t go = (size_t)lr[s] * K + c * 64 + lseg * 8;
            cp16(sb + lso[s],        Ap + go);
            cp16(sb + AMAT + lso[s], Bp + go);
        }
        cp_commit();
    };

    const int arow_lo = wm * 32 + (lane & 15);
    const int akh = lane >> 4;
    const int nrow_lo = (lane & 7) + ((lane >> 4) << 3);
    const int bkh = (lane >> 3) & 1;

    float acc[2][8][4];
    #pragma unroll
    for (int mi = 0; mi < 2; mi++)
        #pragma unroll
        for (int ni = 0; ni < 8; ni++)
            #pragma unroll
            for (int q = 0; q < 4; q++) acc[mi][ni][q] = 0.f;

    load_chunk(0, 0);

    for (int c = 0; c < C; c++) {
        if (c + 1 < C) { load_chunk(c + 1, (c + 1) & 1); cp_wait<1>(); }
        else cp_wait<0>();
        __syncthreads();

        const uint32_t sb = sbase + (c & 1) * BUFB;
        #pragma unroll
        for (int ks = 0; ks < 4; ks++) {
            uint32_t af[2][4];
            #pragma unroll
            for (int mi = 0; mi < 2; mi++) {
                const int r = arow_lo + mi * 16;
                const int seg = ks * 2 + akh;
                const uint32_t off = (uint32_t)(r * 128 + ((seg ^ (r & 7)) << 4));
                ldsm4(af[mi], sb + off);
            }
            uint32_t bf[8][2];
            #pragma unroll
            for (int np = 0; np < 4; np++) {
                const int r = wn * 64 + np * 16 + nrow_lo;
                const int seg = ks * 2 + bkh;
                const uint32_t off = (uint32_t)(r * 128 + ((seg ^ (r & 7)) << 4));
                uint32_t t4[4];
                ldsm4(t4, sb + AMAT + off);
                bf[np * 2][0] = t4[0]; bf[np * 2][1] = t4[1];
                bf[np * 2 + 1][0] = t4[2]; bf[np * 2 + 1][1] = t4[3];
            }
            #pragma unroll
            for (int mi = 0; mi < 2; mi++)
                #pragma unroll
                for (int ni = 0; ni < 8; ni++)
                    mma_f16(acc[mi][ni], af[mi], bf[ni]);
        }
        __syncthreads();
    }

    const float* bp = bias + (size_t)e * NT;
    const int qrow = lane >> 2;
    const int qcol = (lane & 3) * 2;

    #pragma unroll
    for (int mi = 0; mi < 2; mi++) {
        #pragma unroll
        for (int rh = 0; rh < 2; rh++) {
            const int rl = wm * 32 + mi * 16 + qrow + rh * 8;
            const int grow = row0 + rl;
            #pragma unroll
            for (int ni = 0; ni < 8; ni++) {
                const int col = n0 + wn * 64 + ni * 8 + qcol;
                const float2 bb = *(const float2*)(bp + col);
                float v0 = acc[mi][ni][rh * 2 + 0] + bb.x;
                float v1 = acc[mi][ni][rh * 2 + 1] + bb.y;
                v0 = v0 > 0.f ? v0 : 0.2f * v0;
                v1 = v1 > 0.f ? v1 : 0.2f * v1;
                *(uint32_t*)(O16 + (size_t)grow * NT + col) =
                    pk2h(__float2half_rn(v0), __float2half_rn(v1));
            }
        }
    }
}

// ===================== fused layers 2+3 (64-row CTAs, 2 CTAs/SM) ==========
// Stage 1: a2 = leaky(a1[64x512] @ W2^T + b2) -> SMEM fp16, SW128 chunks.
// Stage 2: out = a2 @ W3^T + b3 -> fp32 scatter via perm.
// SMEM: [0, 81920): stage-1 dbuf (A1 8KB + W2 32KB) x2 / stage-2 W3 dbuf 32KB x2
//       [81920, 114688): a2 tile (4 chunks x 8KB)
// Register-dieted (acc reused across stages, loader addrs recomputed) so
// __launch_bounds__(256,2) holds 2 CTAs/SM: 2 x 114688 <= 228KB smem.
#define SM23 114688

__global__ void __launch_bounds__(256, 2) gemm23(
    const __half* __restrict__ A1, const __half* __restrict__ W2,
    const float* __restrict__ b2,  const __half* __restrict__ W3,
    const float* __restrict__ b3,  float* __restrict__ Of)
{
    const int row0 = blockIdx.x * 64;
    if (row0 >= g_padoff[E]) return;

    int e = 0;
    #pragma unroll
    for (int j = 1; j < E; j++)
        if (row0 >= g_padoff[j]) e = j;

    extern __shared__ char smem[];
    const uint32_t sbase = smem_u32(smem);
    const int tid = threadIdx.x;
    const int wid = tid >> 5, lane = tid & 31;
    const int wm = wid & 1, wn = wid >> 1;     // 2M x 4N warp grid

    const __half* Ap  = A1 + (size_t)row0 * H1;
    const __half* B2p = W2 + (size_t)e * H2 * H1;
    const __half* B3p = W3 + (size_t)e * YD * H2;

    const int lseg = tid & 7;

    auto load1 = [&](int c, int buf) {
        const uint32_t sb = sbase + buf * 40960;
        #pragma unroll
        for (int s = 0; s < 2; s++) {
            const int r = (tid + s * 256) >> 3;
            const uint32_t lo = (uint32_t)(r * 128 + ((lseg ^ (r & 7)) << 4));
            cp16(sb + lo, Ap + (size_t)r * H1 + c * 64 + lseg * 8);
        }
        #pragma unroll
        for (int s = 0; s < 8; s++) {
            const int r = (tid + s * 256) >> 3;
            const uint32_t lo = (uint32_t)(r * 128 + ((lseg ^ (r & 7)) << 4));
            cp16(sb + 8192 + lo, B2p + (size_t)r * H1 + c * 64 + lseg * 8);
        }
        cp_commit();
    };
    auto load3 = [&](int c, int buf) {
        const uint32_t sb = sbase + buf * 32768;
        #pragma unroll
        for (int s = 0; s < 8; s++) {
            const int r = (tid + s * 256) >> 3;
            const uint32_t lo = (uint32_t)(r * 128 + ((lseg ^ (r & 7)) << 4));
            cp16(sb + lo, B3p + (size_t)r * H2 + c * 64 + lseg * 8);
        }
        cp_commit();
    };

    const int arow_lo = wm * 32 + (lane & 15);
    const int akh = lane >> 4;
    const int nrow_lo = (lane & 7) + ((lane >> 4) << 3);
    const int bkh = (lane >> 3) & 1;
    const int qrow = lane >> 2;
    const int qcol = (lane & 3) * 2;

    float acc[2][8][4];          // reused by both stages
    #pragma unroll
    for (int mi = 0; mi < 2; mi++)
        #pragma unroll
        for (int ni = 0; ni < 8; ni++)
            #pragma unroll
            for (int q = 0; q < 4; q++) acc[mi][ni][q] = 0.f;

    // ---------- stage 1 ----------
    load1(0, 0);
    for (int c = 0; c < 8; c++) {
        if (c + 1 < 8) { load1(c + 1, (c + 1) & 1); cp_wait<1>(); }
        else cp_wait<0>();
        __syncthreads();

        const uint32_t sb = sbase + (c & 1) * 40960;
        #pragma unroll
        for (int ks = 0; ks < 4; ks++) {
            uint32_t af[2][4];
            #pragma unroll
            for (int mi = 0; mi < 2; mi++) {
                const int r = arow_lo + mi * 16;
                const int seg = ks * 2 + akh;
                const uint32_t off = (uint32_t)(r * 128 + ((seg ^ (r & 7)) << 4));
                ldsm4(af[mi], sb + off);
            }
            uint32_t bf[8][2];
            #pragma unroll
            for (int np = 0; np < 4; np++) {
                const int r = wn * 64 + np * 16 + nrow_lo;
                const int seg = ks * 2 + bkh;
                const uint32_t off = (uint32_t)(r * 128 + ((seg ^ (r & 7)) << 4));
                uint32_t t4[4];
                ldsm4(t4, sb + 8192 + off);
                bf[np * 2][0] = t4[0]; bf[np * 2][1] = t4[1];
                bf[np * 2 + 1][0] = t4[2]; bf[np * 2 + 1][1] = t4[3];
            }
            #pragma unroll
            for (int mi = 0; mi < 2; mi++)
                #pragma unroll
                for (int ni = 0; ni < 8; ni++)
                    mma_f16(acc[mi][ni], af[mi], bf[ni]);
        }
        __syncthreads();
    }

    // stage-1 epilogue: leaky(acc + b2) -> a2 smem (fp16, SW128 chunks of 64 k-cols)
    {
        const float* bp = b2 + (size_t)e * H2;
        #pragma unroll
        for (int mi = 0; mi < 2; mi++) {
            #pragma unroll
            for (int rh = 0; rh < 2; rh++) {
                const int rl = wm * 32 + mi * 16 + qrow + rh * 8;
                #pragma unroll
                for (int ni = 0; ni < 8; ni++) {
                    const int col = wn * 64 + ni * 8 + qcol;
                    const float2 bb = *(const float2*)(bp + col);
                    float v0 = acc[mi][ni][rh * 2 + 0] + bb.x;
                    float v1 = acc[mi][ni][rh * 2 + 1] + bb.y;
                    v0 = v0 > 0.f ? v0 : 0.2f * v0;
                    v1 = v1 > 0.f ? v1 : 0.2f * v1;
                    const uint32_t off = (uint32_t)(rl * 128 + (col & 63) * 2);
                    *(uint32_t*)(smem + 81920 + (col >> 6) * 8192 + SWZ(off)) =
                        pk2h(__float2half_rn(v0), __float2half_rn(v1));
                }
            }
        }
    }
    __syncthreads();

    // ---------- stage 2 (acc reused) ----------
    #pragma unroll
    for (int mi = 0; mi < 2; mi++)
        #pragma unroll
        for (int ni = 0; ni < 8; ni++)
            #pragma unroll
            for (int q = 0; q < 4; q++) acc[mi][ni][q] = 0.f;

    load3(0, 0);
    for (int c = 0; c < 4; c++) {
        if (c + 1 < 4) { load3(c + 1, (c + 1) & 1); cp_wait<1>(); }
        else cp_wait<0>();
        __syncthreads();

        const uint32_t sb  = sbase + (c & 1) * 32768;
        const uint32_t a2b = sbase + 81920 + c * 8192;
        #pragma unroll
        for (int ks = 0; ks < 4; ks++) {
            uint32_t af[2][4];
            #pragma unroll
            for (int mi = 0; mi < 2; mi++) {
                const int r = arow_lo + mi * 16;
                const int seg = ks * 2 + akh;
                const uint32_t off = (uint32_t)(r * 128 + ((seg ^ (r & 7)) << 4));
                ldsm4(af[mi], a2b + off);
            }
            uint32_t bf[8][2];
            #pragma unroll
            for (int np = 0; np < 4; np++) {
                const int r = wn * 64 + np * 16 + nrow_lo;
                const int seg = ks * 2 + bkh;
                const uint32_t off = (uint32_t)(r * 128 + ((seg ^ (r & 7)) << 4));
                uint32_t t4[4];
                ldsm4(t4, sb + off);
                bf[np * 2][0] = t4[0]; bf[np * 2][1] = t4[1];
                bf[np * 2 + 1][0] = t4[2]; bf[np * 2 + 1][1] = t4[3];
            }
            #pragma unroll
            for (int mi = 0; mi < 2; mi++)
                #pragma unroll
                for (int ni = 0; ni < 8; ni++)
                    mma_f16(acc[mi][ni], af[mi], bf[ni]);
        }
        __syncthreads();
    }

    // stage-2 epilogue: bias + scatter fp32
    {
        const float* bp = b3 + (size_t)e * YD;
        #pragma unroll
        for (int mi = 0; mi < 2; mi++) {
            #pragma unroll
            for (int rh = 0; rh < 2; rh++) {
                const int rl = wm * 32 + mi * 16 + qrow + rh * 8;
                const int orig = g_perm[row0 + rl];
                if (orig < 0) continue;
                #pragma unroll
                for (int ni = 0; ni < 8; ni++) {
                    const int col = wn * 64 + ni * 8 + qcol;
                    const float2 bb = *(const float2*)(bp + col);
                    *(float2*)(Of + (size_t)orig * YD + col) =
                        make_float2(acc[mi][ni][rh * 2 + 0] + bb.x,
                                    acc[mi][ni][rh * 2 + 1] + bb.y);
                }
            }
        }
    }
}

// ===================== launch =====================
extern "C" void kernel_launch(void* const* d_in, const int* in_sizes, int n_in,
                              void* d_out, int out_size) {
    const float* h    = (const float*)d_in[0];
    const int*   gate = (const int*)  d_in[1];
    const float* W1   = (const float*)d_in[2];
    const float* b1   = (const float*)d_in[3];
    const float* W2   = (const float*)d_in[4];
    const float* b2   = (const float*)d_in[5];
    const float* W3   = (const float*)d_in[6];
    const float* b3   = (const float*)d_in[7];
    float* out = (float*)d_out;

    cudaFuncSetAttribute(gemm1,  cudaFuncAttributeMaxDynamicSharedMemorySize, SM1);
    cudaFuncSetAttribute(gemm23, cudaFuncAttributeMaxDynamicSharedMemorySize, SM23);

    __half *a16, *a1, *w1, *w2, *w3;
    cudaGetSymbolAddress((void**)&a16, g_A16);
    cudaGetSymbolAddress((void**)&a1,  g_a1);
    cudaGetSymbolAddress((void**)&w1,  g_W1);
    cudaGetSymbolAddress((void**)&w2,  g_W2);
    cudaGetSymbolAddress((void**)&w3,  g_W3);

    route_all<<<1, 1024>>>(gate);
    conv_all<<<3584 + (MAX_ROWS * (DD / 4) + 255) / 256, 256>>>(W1, W2, W3, h);

    gemm1<<<dim3(H1 / 128, MAX_TILES), 256, SM1>>>(a16, w1, b1, a1);
    gemm23<<<MAX_TILES * 2, 256, SM23>>>(a1, w2, b2, w3, b3, out);
}